// round 5
// baseline (speedup 1.0000x reference)
#include <cuda_runtime.h>
#include <cstdint>

#define N_NODES 100000
#define HEADS 8
#define F_IN 128
#define F1 128          // HEADS * 16
#define F2 64           // HEADS * 8
#define NEG_SLOPE 0.2f

// ---------------- static device scratch (no allocations allowed) ----------------
__device__ float g_h1[(size_t)N_NODES * F1];      // layer-1 projected features
__device__ float g_out1[(size_t)N_NODES * F1];    // layer-1 aggregate -> relu -> layer-2 input
__device__ float g_s_src1[(size_t)N_NODES * HEADS];
__device__ float g_s_dst1[(size_t)N_NODES * HEADS];
__device__ float g_denom1[(size_t)N_NODES * HEADS];
__device__ float g_h2[(size_t)N_NODES * F2];
__device__ float g_s_src2[(size_t)N_NODES * HEADS];
__device__ float g_s_dst2[(size_t)N_NODES * HEADS];
__device__ float g_denom2[(size_t)N_NODES * HEADS];
__device__ int   g_idx64;                          // 1 if edge_index is int64, 0 if int32

// ---------------- helpers ----------------
__device__ __forceinline__ void red_add_v4(float* p, float a, float b, float c, float d) {
    asm volatile("red.global.add.v4.f32 [%0], {%1, %2, %3, %4};"
                 :: "l"(p), "f"(a), "f"(b), "f"(c), "f"(d) : "memory");
}

__device__ __forceinline__ float lrelu(float z) {
    return z > 0.f ? z : NEG_SLOPE * z;
}

// Detect edge-index dtype: if the first 256 values interpreted as int64 are all
// valid node ids, it is int64; otherwise (int32 pairs packed) values explode.
__global__ void detect_kernel(const long long* __restrict__ e) {
    long long v = e[threadIdx.x];
    int bad = (v < 0 || v >= (long long)N_NODES);
    int any = __syncthreads_or(bad);
    if (threadIdx.x == 0) g_idx64 = !any;
}

// ---------------- fused GEMM + attention scores + self-loop init ----------------
// h = x @ W            [N, F_OUT]
// s_src[n,h] = <h[n,h,:], a_src[h,:]>, s_dst likewise
// Self-loop seeding:  ex = exp(lrelu(s_src[n,h]+s_dst[n,h]))
//   denom[n,h] = ex ;  out[n,h,:] = ex * h[n,h,:]
template<int F_OUT, int NPB>
__global__ __launch_bounds__(128)
void gemm_scores_kernel(const float* __restrict__ x,
                        const float* __restrict__ W,
                        const float* __restrict__ a_src,
                        const float* __restrict__ a_dst,
                        float* __restrict__ h,
                        float* __restrict__ out,
                        float* __restrict__ s_src,
                        float* __restrict__ s_dst,
                        float* __restrict__ denom) {
    constexpr int NPI = 128 / F_OUT;       // nodes per iteration (1 or 2)
    constexpr int D   = F_OUT / HEADS;     // per-head dim (16 or 8)

    extern __shared__ float sm[];
    float* Ws  = sm;                       // F_IN * F_OUT
    float* xs  = Ws + F_IN * F_OUT;        // NPI * F_IN
    float* as_ = xs + NPI * F_IN;          // F_OUT
    float* ad_ = as_ + F_OUT;              // F_OUT

    const int tid = threadIdx.x;
    for (int i = tid; i < F_IN * F_OUT; i += 128) Ws[i] = W[i];
    if (tid < F_OUT) { as_[tid] = a_src[tid]; ad_[tid] = a_dst[tid]; }

    const int col = tid % F_OUT;
    const int sub = tid / F_OUT;
    const int base = blockIdx.x * NPB;

    for (int it = 0; it < NPB; it += NPI) {
        const int row0 = base + it;
        __syncthreads();
        for (int i = tid; i < NPI * F_IN; i += 128) {
            int r = row0 + i / F_IN;
            xs[i] = (r < N_NODES) ? x[(size_t)r * F_IN + (i % F_IN)] : 0.f;
        }
        __syncthreads();

        const int node = row0 + sub;
        float acc = 0.f;
        const float* xr = xs + sub * F_IN;
        #pragma unroll
        for (int k = 0; k < F_IN; k++) acc = fmaf(xr[k], Ws[k * F_OUT + col], acc);

        if (node < N_NODES) {   // warp-uniform predicate
            float vs = acc * as_[col];
            float vd = acc * ad_[col];
            #pragma unroll
            for (int off = D / 2; off > 0; off >>= 1) {
                vs += __shfl_xor_sync(0xffffffffu, vs, off);
                vd += __shfl_xor_sync(0xffffffffu, vd, off);
            }
            // all D lanes of a head group now hold the full sums
            float ex = __expf(lrelu(vs + vd));   // self-loop term
            size_t oidx = (size_t)node * F_OUT + col;
            h[oidx]   = acc;
            out[oidx] = ex * acc;
            if ((col & (D - 1)) == 0) {
                int head = col / D;
                s_src[(size_t)node * HEADS + head] = vs;
                s_dst[(size_t)node * HEADS + head] = vd;
                denom[(size_t)node * HEADS + head] = ex;
            }
        }
    }
}

// ---------------- edge scatter kernels ----------------
// Layer 1: one warp per edge; lane -> (head = lane/4, dq = lane%4), 4 floats each.
__global__ __launch_bounds__(256)
void edge_l1_kernel(const void* __restrict__ eptr, int E,
                    const float* __restrict__ h,
                    const float* __restrict__ s_src,
                    const float* __restrict__ s_dst,
                    float* __restrict__ out,
                    float* __restrict__ denom) {
    int warp = (blockIdx.x * blockDim.x + threadIdx.x) >> 5;
    if (warp >= E) return;
    int lane = threadIdx.x & 31;

    int src, dst;
    if (g_idx64) {
        const long long* e = (const long long*)eptr;
        src = (int)e[warp];
        dst = (int)e[(size_t)E + warp];
    } else {
        const int* e = (const int*)eptr;
        src = e[warp];
        dst = e[E + warp];
    }

    int head = lane >> 2, dq = lane & 3;
    float z = s_src[(size_t)src * HEADS + head] + s_dst[(size_t)dst * HEADS + head];
    float ex = __expf(lrelu(z));

    const float4 hv = *(const float4*)(h + (size_t)src * F1 + head * 16 + dq * 4);
    red_add_v4(out + (size_t)dst * F1 + head * 16 + dq * 4,
               ex * hv.x, ex * hv.y, ex * hv.z, ex * hv.w);
    if (dq == 0) atomicAdd(denom + (size_t)dst * HEADS + head, ex);
}

// Layer 2: half-warp per edge; sub -> (head = sub/2, dq = sub%2), 4 floats each.
__global__ __launch_bounds__(256)
void edge_l2_kernel(const void* __restrict__ eptr, int E,
                    const float* __restrict__ h,
                    const float* __restrict__ s_src,
                    const float* __restrict__ s_dst,
                    float* __restrict__ out,
                    float* __restrict__ denom) {
    int t = blockIdx.x * blockDim.x + threadIdx.x;
    int e_idx = t >> 4;
    if (e_idx >= E) return;
    int sub = t & 15;

    int src, dst;
    if (g_idx64) {
        const long long* e = (const long long*)eptr;
        src = (int)e[e_idx];
        dst = (int)e[(size_t)E + e_idx];
    } else {
        const int* e = (const int*)eptr;
        src = e[e_idx];
        dst = e[E + e_idx];
    }

    int head = sub >> 1, dq = sub & 1;
    float z = s_src[(size_t)src * HEADS + head] + s_dst[(size_t)dst * HEADS + head];
    float ex = __expf(lrelu(z));

    const float4 hv = *(const float4*)(h + (size_t)src * F2 + head * 8 + dq * 4);
    red_add_v4(out + (size_t)dst * F2 + head * 8 + dq * 4,
               ex * hv.x, ex * hv.y, ex * hv.z, ex * hv.w);
    if (dq == 0) atomicAdd(denom + (size_t)dst * HEADS + head, ex);
}

// ---------------- finalize: normalize + bias (+ relu) ----------------
template<int F_OUT, bool RELU>
__global__ __launch_bounds__(256)
void finalize_kernel(float* __restrict__ out,
                     const float* __restrict__ denom,
                     const float* __restrict__ b) {
    constexpr int D = F_OUT / HEADS;
    size_t idx = (size_t)blockIdx.x * blockDim.x + threadIdx.x;
    if (idx >= (size_t)N_NODES * F_OUT) return;
    int n = (int)(idx / F_OUT);
    int col = (int)(idx % F_OUT);
    int head = col / D;
    float v = out[idx] / (denom[(size_t)n * HEADS + head] + 1e-16f) + b[col];
    if (RELU) v = fmaxf(v, 0.f);
    out[idx] = v;
}

// ---------------- host launcher ----------------
extern "C" void kernel_launch(void* const* d_in, const int* in_sizes, int n_in,
                              void* d_out, int out_size) {
    const float* x    = (const float*)d_in[0];
    const void*  edges = d_in[1];
    const float* W1   = (const float*)d_in[2];
    const float* a1s  = (const float*)d_in[3];
    const float* a1d  = (const float*)d_in[4];
    const float* b1   = (const float*)d_in[5];
    const float* W2   = (const float*)d_in[6];
    const float* a2s  = (const float*)d_in[7];
    const float* a2d  = (const float*)d_in[8];
    const float* b2   = (const float*)d_in[9];
    float* outp = (float*)d_out;

    const int E = in_sizes[1] / 2;

    float *h1, *o1, *ss1, *sd1, *dn1, *h2, *ss2, *sd2, *dn2;
    cudaGetSymbolAddress((void**)&h1,  g_h1);
    cudaGetSymbolAddress((void**)&o1,  g_out1);
    cudaGetSymbolAddress((void**)&ss1, g_s_src1);
    cudaGetSymbolAddress((void**)&sd1, g_s_dst1);
    cudaGetSymbolAddress((void**)&dn1, g_denom1);
    cudaGetSymbolAddress((void**)&h2,  g_h2);
    cudaGetSymbolAddress((void**)&ss2, g_s_src2);
    cudaGetSymbolAddress((void**)&sd2, g_s_dst2);
    cudaGetSymbolAddress((void**)&dn2, g_denom2);

    constexpr int NPB = 64;
    const int smem1 = (F_IN * F1 + 1 * F_IN + 2 * F1) * (int)sizeof(float); // ~67 KB
    const int smem2 = (F_IN * F2 + 2 * F_IN + 2 * F2) * (int)sizeof(float); // ~34 KB
    cudaFuncSetAttribute((const void*)gemm_scores_kernel<F1, NPB>,
                         cudaFuncAttributeMaxDynamicSharedMemorySize, smem1);
    cudaFuncSetAttribute((const void*)gemm_scores_kernel<F2, NPB>,
                         cudaFuncAttributeMaxDynamicSharedMemorySize, smem2);

    const int gemm_blocks = (N_NODES + NPB - 1) / NPB;

    // 0) edge-index dtype detection
    detect_kernel<<<1, 256>>>((const long long*)edges);

    // 1) layer 1: GEMM + scores + self-loop seed
    gemm_scores_kernel<F1, NPB><<<gemm_blocks, 128, smem1>>>(
        x, W1, a1s, a1d, h1, o1, ss1, sd1, dn1);

    // 2) layer 1: edge scatter (warp per edge)
    {
        long long threads = (long long)E * 32;
        int blocks = (int)((threads + 255) / 256);
        edge_l1_kernel<<<blocks, 256>>>(edges, E, h1, ss1, sd1, o1, dn1);
    }

    // 3) layer 1: normalize + bias + relu (in place -> layer-2 input)
    {
        long long total = (long long)N_NODES * F1;
        finalize_kernel<F1, true><<<(int)((total + 255) / 256), 256>>>(o1, dn1, b1);
    }

    // 4) layer 2: GEMM + scores + self-loop seed (accumulate straight into d_out)
    gemm_scores_kernel<F2, NPB><<<gemm_blocks, 128, smem2>>>(
        o1, W2, a2s, a2d, h2, outp, ss2, sd2, dn2);

    // 5) layer 2: edge scatter (half-warp per edge)
    {
        long long threads = (long long)E * 16;
        int blocks = (int)((threads + 255) / 256);
        edge_l2_kernel<<<blocks, 256>>>(edges, E, h2, ss2, sd2, outp, dn2);
    }

    // 6) layer 2: normalize + bias -> final output
    {
        long long total = (long long)N_NODES * F2;
        finalize_kernel<F2, false><<<(int)((total + 255) / 256), 256>>>(outp, dn2, b2);
    }
}

// round 6
// speedup vs baseline: 1.7252x; 1.7252x over previous
#include <cuda_runtime.h>
#include <cstdint>

#define N_NODES 100000
#define HEADS 8
#define F_IN 128
#define F1 128          // HEADS * 16
#define F2 64           // HEADS * 8
#define NEG_SLOPE 0.2f

// ---------------- static device scratch (no allocations allowed) ----------------
__device__ float g_h1[(size_t)N_NODES * F1];      // layer-1 projected features
__device__ float g_out1[(size_t)N_NODES * F1];    // layer-1 aggregate (raw; normalized on the fly in gemm2)
__device__ float g_s_src1[(size_t)N_NODES * HEADS];
__device__ float g_s_dst1[(size_t)N_NODES * HEADS];
__device__ float g_denom1[(size_t)N_NODES * HEADS];
__device__ float g_h2[(size_t)N_NODES * F2];
__device__ float g_s_src2[(size_t)N_NODES * HEADS];
__device__ float g_s_dst2[(size_t)N_NODES * HEADS];
__device__ float g_denom2[(size_t)N_NODES * HEADS];
__device__ int   g_idx64;                          // 1 if edge_index is int64, 0 if int32

// ---------------- helpers ----------------
__device__ __forceinline__ void red_add_v4(float* p, float a, float b, float c, float d) {
    asm volatile("red.global.add.v4.f32 [%0], {%1, %2, %3, %4};"
                 :: "l"(p), "f"(a), "f"(b), "f"(c), "f"(d) : "memory");
}

__device__ __forceinline__ float lrelu(float z) {
    return z > 0.f ? z : NEG_SLOPE * z;
}

// Detect edge-index dtype: if the first 256 values interpreted as int64 are all
// valid node ids, it is int64; otherwise (int32 pairs packed) values explode.
__global__ void detect_kernel(const long long* __restrict__ e) {
    long long v = e[threadIdx.x];
    int bad = (v < 0 || v >= (long long)N_NODES);
    int any = __syncthreads_or(bad);
    if (threadIdx.x == 0) g_idx64 = !any;
}

// ---------------- register-tiled fused GEMM + attention scores + self-loop init ----------------
// Each block: NT nodes x F_OUT cols. Each thread: 4 nodes x 4 cols (16 accumulators).
// x loads are warp-broadcast LDS.128; W loads are float4 LDS -> ~1 B shared traffic / MAC,
// so the kernel runs at the FMA-pipe floor instead of the LDS crossbar floor.
//
// Epilogue per thread: partial s_src/s_dst dot over its 4 cols, butterfly over the
// CGH col-group lanes of the same head, then self-loop seeding:
//   ex = exp(lrelu(s_src+s_dst)); denom = ex; out = ex*h.
// If FUSE_PREV: the xs fill applies   relu(prev / (denom_prev + 1e-16) + b_prev)
// (the previous layer's finalize), eliminating that kernel.
template<int F_OUT, bool FUSE_PREV>
__global__ __launch_bounds__(256)
void gemm_scores_kernel(const float* __restrict__ x,
                        const float* __restrict__ W,
                        const float* __restrict__ a_src,
                        const float* __restrict__ a_dst,
                        const float* __restrict__ dn_prev,
                        const float* __restrict__ b_prev,
                        float* __restrict__ h,
                        float* __restrict__ out,
                        float* __restrict__ s_src,
                        float* __restrict__ s_dst,
                        float* __restrict__ denom) {
    constexpr int CG  = F_OUT / 4;        // col-groups (32 for F1, 16 for F2)
    constexpr int NG  = 256 / CG;         // node-groups (8 / 16)
    constexpr int NT  = NG * 4;           // nodes per block (32 / 64)
    constexpr int D   = F_OUT / HEADS;    // per-head dim (16 / 8)
    constexpr int CGH = D / 4;            // col-groups per head (4 / 2)

    extern __shared__ float sm[];
    float* Ws  = sm;                      // F_IN * F_OUT
    float* xs  = Ws + F_IN * F_OUT;       // NT * F_IN
    float* as_ = xs + NT * F_IN;          // F_OUT
    float* ad_ = as_ + F_OUT;             // F_OUT

    const int tid  = threadIdx.x;
    const int base = blockIdx.x * NT;

    // cooperative loads (all float4)
    for (int i = tid; i < F_IN * F_OUT / 4; i += 256)
        ((float4*)Ws)[i] = ((const float4*)W)[i];
    if (tid < F_OUT) { as_[tid] = a_src[tid]; ad_[tid] = a_dst[tid]; }

    for (int i = tid; i < NT * (F_IN / 4); i += 256) {
        int n  = base + i / (F_IN / 4);
        int cq = i % (F_IN / 4);
        float4 v;
        if (n < N_NODES) {
            v = ((const float4*)x)[(size_t)n * (F_IN / 4) + cq];
            if (FUSE_PREV) {
                // previous layer: F_OUT=128, D=16 -> head = (cq*4)/16 = cq/4
                float inv = 1.f / (dn_prev[(size_t)n * HEADS + (cq >> 2)] + 1e-16f);
                float4 bb = ((const float4*)b_prev)[cq];
                v.x = fmaxf(fmaf(v.x, inv, bb.x), 0.f);
                v.y = fmaxf(fmaf(v.y, inv, bb.y), 0.f);
                v.z = fmaxf(fmaf(v.z, inv, bb.z), 0.f);
                v.w = fmaxf(fmaf(v.w, inv, bb.w), 0.f);
            }
        } else {
            v = make_float4(0.f, 0.f, 0.f, 0.f);
        }
        ((float4*)xs)[i] = v;
    }
    __syncthreads();

    const int cg = tid % CG;
    const int ng = tid / CG;
    const int colbase = cg * 4;
    const float* xbase = xs + ng * 4 * F_IN;

    float acc[4][4] = {};
    #pragma unroll 2
    for (int k4 = 0; k4 < F_IN / 4; ++k4) {
        float xv[4][4];
        #pragma unroll
        for (int m = 0; m < 4; ++m)
            *(float4*)xv[m] = *(const float4*)(xbase + m * F_IN + k4 * 4);
        #pragma unroll
        for (int kk = 0; kk < 4; ++kk) {
            float4 wv = *(const float4*)(Ws + (k4 * 4 + kk) * F_OUT + colbase);
            #pragma unroll
            for (int m = 0; m < 4; ++m) {
                acc[m][0] = fmaf(xv[m][kk], wv.x, acc[m][0]);
                acc[m][1] = fmaf(xv[m][kk], wv.y, acc[m][1]);
                acc[m][2] = fmaf(xv[m][kk], wv.z, acc[m][2]);
                acc[m][3] = fmaf(xv[m][kk], wv.w, acc[m][3]);
            }
        }
    }

    const float a0 = as_[colbase], a1 = as_[colbase + 1],
                a2 = as_[colbase + 2], a3 = as_[colbase + 3];
    const float d0 = ad_[colbase], d1 = ad_[colbase + 1],
                d2 = ad_[colbase + 2], d3 = ad_[colbase + 3];

    #pragma unroll
    for (int m = 0; m < 4; ++m) {
        float vs = acc[m][0]*a0 + acc[m][1]*a1 + acc[m][2]*a2 + acc[m][3]*a3;
        float vd = acc[m][0]*d0 + acc[m][1]*d1 + acc[m][2]*d2 + acc[m][3]*d3;
        #pragma unroll
        for (int off = 1; off < CGH; off <<= 1) {
            vs += __shfl_xor_sync(0xffffffffu, vs, off);
            vd += __shfl_xor_sync(0xffffffffu, vd, off);
        }
        float ex = __expf(lrelu(vs + vd));     // self-loop term
        int node = base + ng * 4 + m;
        if (node < N_NODES) {
            float4 hv = make_float4(acc[m][0], acc[m][1], acc[m][2], acc[m][3]);
            *(float4*)(h + (size_t)node * F_OUT + colbase) = hv;
            float4 ov = make_float4(ex * hv.x, ex * hv.y, ex * hv.z, ex * hv.w);
            *(float4*)(out + (size_t)node * F_OUT + colbase) = ov;
            if ((cg & (CGH - 1)) == 0) {
                int head = cg / CGH;
                s_src[(size_t)node * HEADS + head] = vs;
                s_dst[(size_t)node * HEADS + head] = vd;
                denom[(size_t)node * HEADS + head] = ex;
            }
        }
    }
}

// ---------------- edge scatter kernels ----------------
// Layer 1: one warp per edge; lane -> (head = lane/4, dq = lane%4), 4 floats each.
__global__ __launch_bounds__(256)
void edge_l1_kernel(const void* __restrict__ eptr, int E,
                    const float* __restrict__ h,
                    const float* __restrict__ s_src,
                    const float* __restrict__ s_dst,
                    float* __restrict__ out,
                    float* __restrict__ denom) {
    int warp = (blockIdx.x * blockDim.x + threadIdx.x) >> 5;
    if (warp >= E) return;
    int lane = threadIdx.x & 31;

    int src, dst;
    if (g_idx64) {
        const long long* e = (const long long*)eptr;
        src = (int)e[warp];
        dst = (int)e[(size_t)E + warp];
    } else {
        const int* e = (const int*)eptr;
        src = e[warp];
        dst = e[E + warp];
    }

    int head = lane >> 2, dq = lane & 3;
    float z = s_src[(size_t)src * HEADS + head] + s_dst[(size_t)dst * HEADS + head];
    float ex = __expf(lrelu(z));

    const float4 hv = *(const float4*)(h + (size_t)src * F1 + head * 16 + dq * 4);
    red_add_v4(out + (size_t)dst * F1 + head * 16 + dq * 4,
               ex * hv.x, ex * hv.y, ex * hv.z, ex * hv.w);
    if (dq == 0) atomicAdd(denom + (size_t)dst * HEADS + head, ex);
}

// Layer 2: half-warp per edge; sub -> (head = sub/2, dq = sub%2), 4 floats each.
__global__ __launch_bounds__(256)
void edge_l2_kernel(const void* __restrict__ eptr, int E,
                    const float* __restrict__ h,
                    const float* __restrict__ s_src,
                    const float* __restrict__ s_dst,
                    float* __restrict__ out,
                    float* __restrict__ denom) {
    int t = blockIdx.x * blockDim.x + threadIdx.x;
    int e_idx = t >> 4;
    if (e_idx >= E) return;
    int sub = t & 15;

    int src, dst;
    if (g_idx64) {
        const long long* e = (const long long*)eptr;
        src = (int)e[e_idx];
        dst = (int)e[(size_t)E + e_idx];
    } else {
        const int* e = (const int*)eptr;
        src = e[e_idx];
        dst = e[E + e_idx];
    }

    int head = sub >> 1, dq = sub & 1;
    float z = s_src[(size_t)src * HEADS + head] + s_dst[(size_t)dst * HEADS + head];
    float ex = __expf(lrelu(z));

    const float4 hv = *(const float4*)(h + (size_t)src * F2 + head * 8 + dq * 4);
    red_add_v4(out + (size_t)dst * F2 + head * 8 + dq * 4,
               ex * hv.x, ex * hv.y, ex * hv.z, ex * hv.w);
    if (dq == 0) atomicAdd(denom + (size_t)dst * HEADS + head, ex);
}

// ---------------- finalize (float4): normalize + bias (+ relu) ----------------
template<int F_OUT, bool RELU>
__global__ __launch_bounds__(256)
void finalize4_kernel(float* __restrict__ out,
                      const float* __restrict__ denom,
                      const float* __restrict__ b) {
    constexpr int D = F_OUT / HEADS;
    constexpr int Q = F_OUT / 4;          // float4 per row
    size_t i = (size_t)blockIdx.x * blockDim.x + threadIdx.x;
    if (i >= (size_t)N_NODES * Q) return;
    int n  = (int)(i / Q);
    int cq = (int)(i % Q);
    int head = (cq * 4) / D;
    float inv = 1.f / (denom[(size_t)n * HEADS + head] + 1e-16f);
    float4 v  = ((float4*)out)[i];
    float4 bb = ((const float4*)b)[cq];
    v.x = fmaf(v.x, inv, bb.x);
    v.y = fmaf(v.y, inv, bb.y);
    v.z = fmaf(v.z, inv, bb.z);
    v.w = fmaf(v.w, inv, bb.w);
    if (RELU) {
        v.x = fmaxf(v.x, 0.f); v.y = fmaxf(v.y, 0.f);
        v.z = fmaxf(v.z, 0.f); v.w = fmaxf(v.w, 0.f);
    }
    ((float4*)out)[i] = v;
}

// ---------------- host launcher ----------------
extern "C" void kernel_launch(void* const* d_in, const int* in_sizes, int n_in,
                              void* d_out, int out_size) {
    const float* x     = (const float*)d_in[0];
    const void*  edges = d_in[1];
    const float* W1    = (const float*)d_in[2];
    const float* a1s   = (const float*)d_in[3];
    const float* a1d   = (const float*)d_in[4];
    const float* b1    = (const float*)d_in[5];
    const float* W2    = (const float*)d_in[6];
    const float* a2s   = (const float*)d_in[7];
    const float* a2d   = (const float*)d_in[8];
    const float* b2    = (const float*)d_in[9];
    float* outp = (float*)d_out;

    const int E = in_sizes[1] / 2;

    float *h1, *o1, *ss1, *sd1, *dn1, *h2, *ss2, *sd2, *dn2;
    cudaGetSymbolAddress((void**)&h1,  g_h1);
    cudaGetSymbolAddress((void**)&o1,  g_out1);
    cudaGetSymbolAddress((void**)&ss1, g_s_src1);
    cudaGetSymbolAddress((void**)&sd1, g_s_dst1);
    cudaGetSymbolAddress((void**)&dn1, g_denom1);
    cudaGetSymbolAddress((void**)&h2,  g_h2);
    cudaGetSymbolAddress((void**)&ss2, g_s_src2);
    cudaGetSymbolAddress((void**)&sd2, g_s_dst2);
    cudaGetSymbolAddress((void**)&dn2, g_denom2);

    // smem: W tile + x tile + a_src + a_dst
    constexpr int NT1 = 32, NT2 = 64;
    const int smem1 = (F_IN * F1 + NT1 * F_IN + 2 * F1) * (int)sizeof(float); // ~83 KB
    const int smem2 = (F_IN * F2 + NT2 * F_IN + 2 * F2) * (int)sizeof(float); // ~66 KB
    cudaFuncSetAttribute((const void*)gemm_scores_kernel<F1, false>,
                         cudaFuncAttributeMaxDynamicSharedMemorySize, smem1);
    cudaFuncSetAttribute((const void*)gemm_scores_kernel<F2, true>,
                         cudaFuncAttributeMaxDynamicSharedMemorySize, smem2);

    // 0) edge-index dtype detection
    detect_kernel<<<1, 256>>>((const long long*)edges);

    // 1) layer 1: GEMM + scores + self-loop seed
    gemm_scores_kernel<F1, false><<<(N_NODES + NT1 - 1) / NT1, 256, smem1>>>(
        x, W1, a1s, a1d, nullptr, nullptr, h1, o1, ss1, sd1, dn1);

    // 2) layer 1: edge scatter (warp per edge)
    {
        long long threads = (long long)E * 32;
        edge_l1_kernel<<<(int)((threads + 255) / 256), 256>>>(edges, E, h1, ss1, sd1, o1, dn1);
    }

    // 3) layer 2: GEMM with fused layer-1 finalize (normalize+bias+relu on load)
    gemm_scores_kernel<F2, true><<<(N_NODES + NT2 - 1) / NT2, 256, smem2>>>(
        o1, W2, a2s, a2d, dn1, b1, h2, outp, ss2, sd2, dn2);

    // 4) layer 2: edge scatter (half-warp per edge)
    {
        long long threads = (long long)E * 16;
        edge_l2_kernel<<<(int)((threads + 255) / 256), 256>>>(edges, E, h2, ss2, sd2, outp, dn2);
    }

    // 5) layer 2: normalize + bias -> final output
    {
        long long total = (long long)N_NODES * (F2 / 4);
        finalize4_kernel<F2, false><<<(int)((total + 255) / 256), 256>>>(outp, dn2, b2);
    }
}

// round 11
// speedup vs baseline: 2.8192x; 1.6342x over previous
#include <cuda_runtime.h>
#include <cstdint>

#define N_NODES 100000
#define HEADS 8
#define F_IN 128
#define F1 128          // HEADS * 16
#define F2 64           // HEADS * 8
#define NEG_SLOPE 0.2f
#define MAX_E 1800000

// ---------------- static device scratch (no allocations allowed) ----------------
__device__ float g_h1[(size_t)N_NODES * F1];      // layer-1 projected features
__device__ float g_out1[(size_t)N_NODES * F1];    // layer-1 output (normalized+bias+relu)
__device__ float g_s_src1[(size_t)N_NODES * HEADS];
__device__ float g_s_dst1[(size_t)N_NODES * HEADS];
__device__ float g_h2[(size_t)N_NODES * F2];
__device__ float g_s_src2[(size_t)N_NODES * HEADS];
__device__ float g_s_dst2[(size_t)N_NODES * HEADS];
__device__ int   g_idx64;                          // 1 if edge_index is int64, 0 if int32

// CSR-by-destination (rebuilt every launch; graph inputs are constant per call)
__device__ int g_deg[N_NODES];
__device__ int g_off[N_NODES + 1];
__device__ int g_cur[N_NODES];
__device__ int g_bsum[256];
__device__ int g_src_sorted[MAX_E];

// ---------------- helpers ----------------
__device__ __forceinline__ float lrelu(float z) {
    return z > 0.f ? z : NEG_SLOPE * z;
}

// Detect edge-index dtype: if the first 256 values interpreted as int64 are all
// valid node ids, it is int64; otherwise (int32 pairs packed) values explode.
__global__ void detect_kernel(const long long* __restrict__ e) {
    long long v = e[threadIdx.x];
    int bad = (v < 0 || v >= (long long)N_NODES);
    int any = __syncthreads_or(bad);
    if (threadIdx.x == 0) g_idx64 = !any;
}

// ---------------- CSR build: histogram -> scan -> scatter ----------------
__global__ __launch_bounds__(256)
void hist_kernel(const void* __restrict__ eptr, int E) {
    int i = blockIdx.x * blockDim.x + threadIdx.x;
    if (i >= E) return;
    int dst = g_idx64 ? (int)((const long long*)eptr)[(size_t)E + i]
                      : ((const int*)eptr)[E + i];
    atomicAdd(&g_deg[dst], 1);
}

// block-local exclusive scan over 512 elements; block totals to g_bsum
__global__ __launch_bounds__(512)
void scan1_kernel() {
    __shared__ int wsum[16];
    int i = blockIdx.x * 512 + threadIdx.x;
    int lane = threadIdx.x & 31, wid = threadIdx.x >> 5;
    int v = (i < N_NODES) ? g_deg[i] : 0;
    int s = v;
    #pragma unroll
    for (int off = 1; off < 32; off <<= 1) {
        int t = __shfl_up_sync(0xffffffffu, s, off);
        if (lane >= off) s += t;
    }
    if (lane == 31) wsum[wid] = s;
    __syncthreads();
    if (wid == 0) {
        int t = (lane < 16) ? wsum[lane] : 0;
        #pragma unroll
        for (int off = 1; off < 16; off <<= 1) {
            int u = __shfl_up_sync(0xffffffffu, t, off);
            if (lane >= off) t += u;
        }
        if (lane < 16) wsum[lane] = t;
    }
    __syncthreads();
    int base = wid ? wsum[wid - 1] : 0;
    if (i < N_NODES) g_off[i] = base + s - v;
    if (threadIdx.x == 0) g_bsum[blockIdx.x] = wsum[15];
}

// exclusive scan of the (<=256) block sums, single block
__global__ __launch_bounds__(256)
void scan2_kernel(int nb) {
    __shared__ int wsum[8];
    int lane = threadIdx.x & 31, wid = threadIdx.x >> 5;
    int v = (threadIdx.x < nb) ? g_bsum[threadIdx.x] : 0;
    int s = v;
    #pragma unroll
    for (int off = 1; off < 32; off <<= 1) {
        int t = __shfl_up_sync(0xffffffffu, s, off);
        if (lane >= off) s += t;
    }
    if (lane == 31) wsum[wid] = s;
    __syncthreads();
    if (wid == 0) {
        int t = (lane < 8) ? wsum[lane] : 0;
        #pragma unroll
        for (int off = 1; off < 8; off <<= 1) {
            int u = __shfl_up_sync(0xffffffffu, t, off);
            if (lane >= off) t += u;
        }
        if (lane < 8) wsum[lane] = t;
    }
    __syncthreads();
    int base = wid ? wsum[wid - 1] : 0;
    if (threadIdx.x < nb) g_bsum[threadIdx.x] = base + s - v;
}

__global__ __launch_bounds__(512)
void scan3_kernel(int E) {
    int i = blockIdx.x * 512 + threadIdx.x;
    if (i < N_NODES) {
        int o = g_off[i] + g_bsum[blockIdx.x];
        g_off[i] = o;
        g_cur[i] = o;
    }
    if (i == 0) g_off[N_NODES] = E;
}

__global__ __launch_bounds__(256)
void scatter_kernel(const void* __restrict__ eptr, int E) {
    int i = blockIdx.x * blockDim.x + threadIdx.x;
    if (i >= E) return;
    int src, dst;
    if (g_idx64) {
        const long long* e = (const long long*)eptr;
        src = (int)e[i];
        dst = (int)e[(size_t)E + i];
    } else {
        const int* e = (const int*)eptr;
        src = e[i];
        dst = e[E + i];
    }
    int pos = atomicAdd(&g_cur[dst], 1);
    g_src_sorted[pos] = src;
}

// ---------------- register-tiled fused GEMM + attention scores ----------------
// Each block: NT nodes x F_OUT cols. Each thread: 4 nodes x 4 cols (16 accumulators).
// Outputs: h = x@W, s_src[n,h] = <h[n,h,:],a_src[h,:]>, s_dst likewise.
template<int F_OUT>
__global__ __launch_bounds__(256)
void gemm_scores_kernel(const float* __restrict__ x,
                        const float* __restrict__ W,
                        const float* __restrict__ a_src,
                        const float* __restrict__ a_dst,
                        float* __restrict__ h,
                        float* __restrict__ s_src,
                        float* __restrict__ s_dst) {
    constexpr int CG  = F_OUT / 4;        // col-groups (32 for F1, 16 for F2)
    constexpr int NG  = 256 / CG;         // node-groups (8 / 16)
    constexpr int NT  = NG * 4;           // nodes per block (32 / 64)
    constexpr int D   = F_OUT / HEADS;    // per-head dim (16 / 8)
    constexpr int CGH = D / 4;            // col-groups per head (4 / 2)

    extern __shared__ float sm[];
    float* Ws  = sm;                      // F_IN * F_OUT
    float* xs  = Ws + F_IN * F_OUT;       // NT * F_IN
    float* as_ = xs + NT * F_IN;          // F_OUT
    float* ad_ = as_ + F_OUT;             // F_OUT

    const int tid  = threadIdx.x;
    const int base = blockIdx.x * NT;

    for (int i = tid; i < F_IN * F_OUT / 4; i += 256)
        ((float4*)Ws)[i] = ((const float4*)W)[i];
    if (tid < F_OUT) { as_[tid] = a_src[tid]; ad_[tid] = a_dst[tid]; }

    for (int i = tid; i < NT * (F_IN / 4); i += 256) {
        int n  = base + i / (F_IN / 4);
        int cq = i % (F_IN / 4);
        float4 v = (n < N_NODES) ? ((const float4*)x)[(size_t)n * (F_IN / 4) + cq]
                                 : make_float4(0.f, 0.f, 0.f, 0.f);
        ((float4*)xs)[i] = v;
    }
    __syncthreads();

    const int cg = tid % CG;
    const int ng = tid / CG;
    const int colbase = cg * 4;
    const float* xbase = xs + ng * 4 * F_IN;

    float acc[4][4] = {};
    #pragma unroll 2
    for (int k4 = 0; k4 < F_IN / 4; ++k4) {
        float xv[4][4];
        #pragma unroll
        for (int m = 0; m < 4; ++m)
            *(float4*)xv[m] = *(const float4*)(xbase + m * F_IN + k4 * 4);
        #pragma unroll
        for (int kk = 0; kk < 4; ++kk) {
            float4 wv = *(const float4*)(Ws + (k4 * 4 + kk) * F_OUT + colbase);
            #pragma unroll
            for (int m = 0; m < 4; ++m) {
                acc[m][0] = fmaf(xv[m][kk], wv.x, acc[m][0]);
                acc[m][1] = fmaf(xv[m][kk], wv.y, acc[m][1]);
                acc[m][2] = fmaf(xv[m][kk], wv.z, acc[m][2]);
                acc[m][3] = fmaf(xv[m][kk], wv.w, acc[m][3]);
            }
        }
    }

    const float a0 = as_[colbase], a1 = as_[colbase + 1],
                a2 = as_[colbase + 2], a3 = as_[colbase + 3];
    const float d0 = ad_[colbase], d1 = ad_[colbase + 1],
                d2 = ad_[colbase + 2], d3 = ad_[colbase + 3];

    #pragma unroll
    for (int m = 0; m < 4; ++m) {
        float vs = acc[m][0]*a0 + acc[m][1]*a1 + acc[m][2]*a2 + acc[m][3]*a3;
        float vd = acc[m][0]*d0 + acc[m][1]*d1 + acc[m][2]*d2 + acc[m][3]*d3;
        #pragma unroll
        for (int off = 1; off < CGH; off <<= 1) {
            vs += __shfl_xor_sync(0xffffffffu, vs, off);
            vd += __shfl_xor_sync(0xffffffffu, vd, off);
        }
        int node = base + ng * 4 + m;
        if (node < N_NODES) {
            *(float4*)(h + (size_t)node * F_OUT + colbase) =
                make_float4(acc[m][0], acc[m][1], acc[m][2], acc[m][3]);
            if ((cg & (CGH - 1)) == 0) {
                int head = cg / CGH;
                s_src[(size_t)node * HEADS + head] = vs;
                s_dst[(size_t)node * HEADS + head] = vd;
            }
        }
    }
}

// ---------------- gather aggregation: one (F_OUT/4)-lane group per dst ----------------
// Self-loop seeded analytically; edges walked from the dst-sorted CSR; row written
// once, coalesced, already normalized + bias (+relu). No atomics anywhere.
template<int F_OUT, bool RELU>
__global__ __launch_bounds__(256)
void aggregate_kernel(const float* __restrict__ h,
                      const float* __restrict__ s_src,
                      const float* __restrict__ s_dst,
                      const float* __restrict__ b,
                      float* __restrict__ out) {
    constexpr int LPD = F_OUT / 4;        // lanes per dst (32 / 16)
    constexpr int D   = F_OUT / HEADS;
    int gt  = blockIdx.x * 256 + threadIdx.x;
    int dst = gt / LPD;
    if (dst >= N_NODES) return;
    int sub  = gt % LPD;
    int head = (sub * 4) / D;

    float sd = s_dst[(size_t)dst * HEADS + head];

    // self-loop
    float ex = __expf(lrelu(s_src[(size_t)dst * HEADS + head] + sd));
    float4 hv = *(const float4*)(h + (size_t)dst * F_OUT + sub * 4);
    float ax = ex * hv.x, ay = ex * hv.y, az = ex * hv.z, aw = ex * hv.w;
    float den = ex;

    int i = g_off[dst], end = g_off[dst + 1];
    for (; i + 2 <= end; i += 2) {
        int s0 = g_src_sorted[i];
        int s1 = g_src_sorted[i + 1];
        float z0 = s_src[(size_t)s0 * HEADS + head];
        float z1 = s_src[(size_t)s1 * HEADS + head];
        float4 v0 = *(const float4*)(h + (size_t)s0 * F_OUT + sub * 4);
        float4 v1 = *(const float4*)(h + (size_t)s1 * F_OUT + sub * 4);
        float e0 = __expf(lrelu(z0 + sd));
        float e1 = __expf(lrelu(z1 + sd));
        ax = fmaf(e0, v0.x, ax); ay = fmaf(e0, v0.y, ay);
        az = fmaf(e0, v0.z, az); aw = fmaf(e0, v0.w, aw);
        ax = fmaf(e1, v1.x, ax); ay = fmaf(e1, v1.y, ay);
        az = fmaf(e1, v1.z, az); aw = fmaf(e1, v1.w, aw);
        den += e0 + e1;
    }
    if (i < end) {
        int s0 = g_src_sorted[i];
        float e0 = __expf(lrelu(s_src[(size_t)s0 * HEADS + head] + sd));
        float4 v0 = *(const float4*)(h + (size_t)s0 * F_OUT + sub * 4);
        ax = fmaf(e0, v0.x, ax); ay = fmaf(e0, v0.y, ay);
        az = fmaf(e0, v0.z, az); aw = fmaf(e0, v0.w, aw);
        den += e0;
    }

    float inv = 1.f / (den + 1e-16f);
    float4 bb = ((const float4*)b)[sub];
    float4 o;
    o.x = fmaf(ax, inv, bb.x);
    o.y = fmaf(ay, inv, bb.y);
    o.z = fmaf(az, inv, bb.z);
    o.w = fmaf(aw, inv, bb.w);
    if (RELU) {
        o.x = fmaxf(o.x, 0.f); o.y = fmaxf(o.y, 0.f);
        o.z = fmaxf(o.z, 0.f); o.w = fmaxf(o.w, 0.f);
    }
    *(float4*)(out + (size_t)dst * F_OUT + sub * 4) = o;
}

// ---------------- host launcher ----------------
extern "C" void kernel_launch(void* const* d_in, const int* in_sizes, int n_in,
                              void* d_out, int out_size) {
    const float* x     = (const float*)d_in[0];
    const void*  edges = d_in[1];
    const float* W1    = (const float*)d_in[2];
    const float* a1s   = (const float*)d_in[3];
    const float* a1d   = (const float*)d_in[4];
    const float* b1    = (const float*)d_in[5];
    const float* W2    = (const float*)d_in[6];
    const float* a2s   = (const float*)d_in[7];
    const float* a2d   = (const float*)d_in[8];
    const float* b2    = (const float*)d_in[9];
    float* outp = (float*)d_out;

    const int E = in_sizes[1] / 2;

    float *h1, *o1, *ss1, *sd1, *h2, *ss2, *sd2;
    int* degp;
    cudaGetSymbolAddress((void**)&h1,  g_h1);
    cudaGetSymbolAddress((void**)&o1,  g_out1);
    cudaGetSymbolAddress((void**)&ss1, g_s_src1);
    cudaGetSymbolAddress((void**)&sd1, g_s_dst1);
    cudaGetSymbolAddress((void**)&h2,  g_h2);
    cudaGetSymbolAddress((void**)&ss2, g_s_src2);
    cudaGetSymbolAddress((void**)&sd2, g_s_dst2);
    cudaGetSymbolAddress((void**)&degp, g_deg);

    constexpr int NT1 = 32, NT2 = 64;
    const int smem1 = (F_IN * F1 + NT1 * F_IN + 2 * F1) * (int)sizeof(float); // ~83 KB
    const int smem2 = (F_IN * F2 + NT2 * F_IN + 2 * F2) * (int)sizeof(float); // ~66 KB
    cudaFuncSetAttribute((const void*)gemm_scores_kernel<F1>,
                         cudaFuncAttributeMaxDynamicSharedMemorySize, smem1);
    cudaFuncSetAttribute((const void*)gemm_scores_kernel<F2>,
                         cudaFuncAttributeMaxDynamicSharedMemorySize, smem2);

    const int eblocks   = (E + 255) / 256;
    const int nscan     = (N_NODES + 511) / 512;   // 196 blocks

    // 0) dtype detect + CSR build (graph constant; ~25us)
    detect_kernel<<<1, 256>>>((const long long*)edges);
    cudaMemsetAsync(degp, 0, N_NODES * sizeof(int));
    hist_kernel<<<eblocks, 256>>>(edges, E);
    scan1_kernel<<<nscan, 512>>>();
    scan2_kernel<<<1, 256>>>(nscan);
    scan3_kernel<<<nscan, 512>>>(E);
    scatter_kernel<<<eblocks, 256>>>(edges, E);

    // 1) layer 1: GEMM + scores
    gemm_scores_kernel<F1><<<(N_NODES + NT1 - 1) / NT1, 256, smem1>>>(
        x, W1, a1s, a1d, h1, ss1, sd1);

    // 2) layer 1: gather-aggregate (+normalize +bias +relu fused)
    aggregate_kernel<F1, true><<<(N_NODES * (F1 / 4) + 255) / 256, 256>>>(
        h1, ss1, sd1, b1, o1);

    // 3) layer 2: GEMM + scores
    gemm_scores_kernel<F2><<<(N_NODES + NT2 - 1) / NT2, 256, smem2>>>(
        o1, W2, a2s, a2d, h2, ss2, sd2);

    // 4) layer 2: gather-aggregate (+normalize +bias) -> final output
    aggregate_kernel<F2, false><<<(N_NODES * (F2 / 4) + 255) / 256, 256>>>(
        h2, ss2, sd2, b2, outp);
}

// round 12
// speedup vs baseline: 3.1373x; 1.1128x over previous
#include <cuda_runtime.h>
#include <cstdint>

#define N_NODES 100000
#define HEADS 8
#define F_IN 128
#define F1 128          // HEADS * 16
#define F2 64           // HEADS * 8
#define NEG_SLOPE 0.2f
#define MAX_E 1800000

// ---------------- static device scratch (no allocations allowed) ----------------
__device__ float g_h1[(size_t)N_NODES * F1];      // layer-1 projected features
__device__ float g_out1[(size_t)N_NODES * F1];    // layer-1 output (normalized+bias+relu)
__device__ float g_s_src1[(size_t)N_NODES * HEADS];
__device__ float g_s_dst1[(size_t)N_NODES * HEADS];
__device__ float g_h2[(size_t)N_NODES * F2];
__device__ float g_s_src2[(size_t)N_NODES * HEADS];
__device__ float g_s_dst2[(size_t)N_NODES * HEADS];
__device__ int   g_idx64;                          // 1 if edge_index is int64, 0 if int32

// transposed weights: WT[col][k]
__device__ float g_WT1[F_IN * F1];
__device__ float g_WT2[F_IN * F2];

// CSR-by-destination (rebuilt every launch; graph inputs are constant per call)
__device__ int g_deg[N_NODES];
__device__ int g_off[N_NODES + 1];
__device__ int g_cur[N_NODES];
__device__ int g_bsum[256];
__device__ int g_src_sorted[MAX_E];

// ---------------- helpers ----------------
__device__ __forceinline__ float lrelu(float z) {
    return z > 0.f ? z : NEG_SLOPE * z;
}

// packed dual-fp32 FMA (sm_100+): d.lo += a.lo*b.lo ; d.hi += a.hi*b.hi
__device__ __forceinline__ void fma2(unsigned long long& d,
                                     unsigned long long a,
                                     unsigned long long b) {
    asm("fma.rn.f32x2 %0, %1, %2, %0;" : "+l"(d) : "l"(a), "l"(b));
}

__device__ __forceinline__ float pair_sum(unsigned long long v) {
    float lo = __uint_as_float((unsigned)(v & 0xffffffffULL));
    float hi = __uint_as_float((unsigned)(v >> 32));
    return lo + hi;
}

// Detect edge-index dtype: if the first 256 values interpreted as int64 are all
// valid node ids, it is int64; otherwise (int32 pairs packed) values explode.
__global__ void detect_kernel(const long long* __restrict__ e) {
    long long v = e[threadIdx.x];
    int bad = (v < 0 || v >= (long long)N_NODES);
    int any = __syncthreads_or(bad);
    if (threadIdx.x == 0) g_idx64 = !any;
}

// ---------------- weight transpose (once per launch, tiny) ----------------
__global__ __launch_bounds__(256)
void transpose_kernel(const float* __restrict__ W1, const float* __restrict__ W2) {
    int t = blockIdx.x * 256 + threadIdx.x;
    if (t < F_IN * F1) {
        int c = t / F_IN, k = t % F_IN;
        g_WT1[t] = W1[k * F1 + c];
    } else {
        int u = t - F_IN * F1;
        if (u < F_IN * F2) {
            int c = u / F_IN, k = u % F_IN;
            g_WT2[u] = W2[k * F2 + c];
        }
    }
}

// ---------------- CSR build: histogram -> scan -> scatter ----------------
__global__ __launch_bounds__(256)
void hist_kernel(const void* __restrict__ eptr, int E) {
    int i = blockIdx.x * blockDim.x + threadIdx.x;
    if (i >= E) return;
    int dst = g_idx64 ? (int)((const long long*)eptr)[(size_t)E + i]
                      : ((const int*)eptr)[E + i];
    atomicAdd(&g_deg[dst], 1);
}

// block-local exclusive scan over 512 elements; block totals to g_bsum
__global__ __launch_bounds__(512)
void scan1_kernel() {
    __shared__ int wsum[16];
    int i = blockIdx.x * 512 + threadIdx.x;
    int lane = threadIdx.x & 31, wid = threadIdx.x >> 5;
    int v = (i < N_NODES) ? g_deg[i] : 0;
    int s = v;
    #pragma unroll
    for (int off = 1; off < 32; off <<= 1) {
        int t = __shfl_up_sync(0xffffffffu, s, off);
        if (lane >= off) s += t;
    }
    if (lane == 31) wsum[wid] = s;
    __syncthreads();
    if (wid == 0) {
        int t = (lane < 16) ? wsum[lane] : 0;
        #pragma unroll
        for (int off = 1; off < 16; off <<= 1) {
            int u = __shfl_up_sync(0xffffffffu, t, off);
            if (lane >= off) t += u;
        }
        if (lane < 16) wsum[lane] = t;
    }
    __syncthreads();
    int base = wid ? wsum[wid - 1] : 0;
    if (i < N_NODES) g_off[i] = base + s - v;
    if (threadIdx.x == 0) g_bsum[blockIdx.x] = wsum[15];
}

// exclusive scan of the (<=256) block sums, single block
__global__ __launch_bounds__(256)
void scan2_kernel(int nb) {
    __shared__ int wsum[8];
    int lane = threadIdx.x & 31, wid = threadIdx.x >> 5;
    int v = (threadIdx.x < nb) ? g_bsum[threadIdx.x] : 0;
    int s = v;
    #pragma unroll
    for (int off = 1; off < 32; off <<= 1) {
        int t = __shfl_up_sync(0xffffffffu, s, off);
        if (lane >= off) s += t;
    }
    if (lane == 31) wsum[wid] = s;
    __syncthreads();
    if (wid == 0) {
        int t = (lane < 8) ? wsum[lane] : 0;
        #pragma unroll
        for (int off = 1; off < 8; off <<= 1) {
            int u = __shfl_up_sync(0xffffffffu, t, off);
            if (lane >= off) t += u;
        }
        if (lane < 8) wsum[lane] = t;
    }
    __syncthreads();
    int base = wid ? wsum[wid - 1] : 0;
    if (threadIdx.x < nb) g_bsum[threadIdx.x] = base + s - v;
}

__global__ __launch_bounds__(512)
void scan3_kernel(int E) {
    int i = blockIdx.x * 512 + threadIdx.x;
    if (i < N_NODES) {
        int o = g_off[i] + g_bsum[blockIdx.x];
        g_off[i] = o;
        g_cur[i] = o;
    }
    if (i == 0) g_off[N_NODES] = E;
}

__global__ __launch_bounds__(256)
void scatter_kernel(const void* __restrict__ eptr, int E) {
    int i = blockIdx.x * blockDim.x + threadIdx.x;
    if (i >= E) return;
    int src, dst;
    if (g_idx64) {
        const long long* e = (const long long*)eptr;
        src = (int)e[i];
        dst = (int)e[(size_t)E + i];
    } else {
        const int* e = (const int*)eptr;
        src = e[i];
        dst = e[E + i];
    }
    int pos = atomicAdd(&g_cur[dst], 1);
    g_src_sorted[pos] = src;
}

// ---------------- FFMA2 register-tiled fused GEMM + attention scores ----------------
// W transposed ([col][k]) with XOR-chunk swizzle in SMEM -> packed dual-fp32 FMAs
// pair along k with zero packing MOVs. Each thread: 4 nodes x 4 cols, accumulators
// are 64-bit (even-k, odd-k) partial-sum pairs.
// Outputs: h = x@W, s_src[n,h] = <h[n,h,:],a_src[h,:]>, s_dst likewise.
template<int F_OUT, int NT>
__global__ __launch_bounds__(512)
void gemm_scores_kernel(const float* __restrict__ x,
                        const float* __restrict__ WT,   // [F_OUT][F_IN] transposed
                        const float* __restrict__ a_src,
                        const float* __restrict__ a_dst,
                        float* __restrict__ h,
                        float* __restrict__ s_src,
                        float* __restrict__ s_dst) {
    constexpr int CG   = F_OUT / 4;      // col-groups (32 for F1, 16 for F2)
    constexpr int NG   = 512 / CG;       // node-groups (16 / 32)
    static_assert(NT == NG * 4, "tile mismatch");
    constexpr int D    = F_OUT / HEADS;  // per-head dim (16 / 8)
    constexpr int CGH  = D / 4;          // col-groups per head (4 / 2)
    constexpr int XROW = F_IN + 4;       // padded xs row (132 floats, 16B-multiple)

    extern __shared__ float sm[];
    float* Ws  = sm;                     // F_OUT * F_IN (swizzled, col-major rows)
    float* xs  = Ws + F_OUT * F_IN;      // NT * XROW
    float* as_ = xs + NT * XROW;         // F_OUT
    float* ad_ = as_ + F_OUT;            // F_OUT

    const int tid  = threadIdx.x;
    const int base = blockIdx.x * NT;

    // W fill: row r (= output col), chunk q of 4 floats; swizzle chunk ^= (r>>2)&7
    for (int i = tid; i < F_OUT * (F_IN / 4); i += 512) {
        int r = i >> 5, q = i & 31;
        *(float4*)(Ws + r * F_IN + (((q) ^ ((r >> 2) & 7)) << 2)) =
            ((const float4*)WT)[i];
    }
    if (tid < F_OUT) { as_[tid] = a_src[tid]; ad_[tid] = a_dst[tid]; }

    // xs fill (padded rows)
    for (int i = tid; i < NT * (F_IN / 4); i += 512) {
        int nl = i >> 5, cq = i & 31;
        int n  = base + nl;
        float4 v = (n < N_NODES) ? ((const float4*)x)[(size_t)n * (F_IN / 4) + cq]
                                 : make_float4(0.f, 0.f, 0.f, 0.f);
        *(float4*)(xs + nl * XROW + cq * 4) = v;
    }
    __syncthreads();

    const int cg = tid % CG;
    const int ng = tid / CG;
    const int colbase = cg * 4;
    const int swz = (cg & 7) << 2;       // word-offset XOR for swizzled W reads
    const float* xbase = xs + ng * 4 * XROW;
    const float* wr0 = Ws + (colbase + 0) * F_IN;
    const float* wr1 = Ws + (colbase + 1) * F_IN;
    const float* wr2 = Ws + (colbase + 2) * F_IN;
    const float* wr3 = Ws + (colbase + 3) * F_IN;

    unsigned long long acc[4][4] = {};   // [node][col], packed (even-k, odd-k)

    #pragma unroll 2
    for (int k4 = 0; k4 < F_IN / 4; ++k4) {
        ulonglong2 xp[4];
        #pragma unroll
        for (int m = 0; m < 4; ++m)
            xp[m] = *(const ulonglong2*)(xbase + m * XROW + k4 * 4);

        const int ko = (k4 * 4) ^ swz;
        ulonglong2 w0 = *(const ulonglong2*)(wr0 + ko);
        ulonglong2 w1 = *(const ulonglong2*)(wr1 + ko);
        ulonglong2 w2 = *(const ulonglong2*)(wr2 + ko);
        ulonglong2 w3 = *(const ulonglong2*)(wr3 + ko);

        #pragma unroll
        for (int m = 0; m < 4; ++m) {
            fma2(acc[m][0], xp[m].x, w0.x); fma2(acc[m][0], xp[m].y, w0.y);
            fma2(acc[m][1], xp[m].x, w1.x); fma2(acc[m][1], xp[m].y, w1.y);
            fma2(acc[m][2], xp[m].x, w2.x); fma2(acc[m][2], xp[m].y, w2.y);
            fma2(acc[m][3], xp[m].x, w3.x); fma2(acc[m][3], xp[m].y, w3.y);
        }
    }

    const float a0 = as_[colbase], a1 = as_[colbase + 1],
                a2 = as_[colbase + 2], a3 = as_[colbase + 3];
    const float d0 = ad_[colbase], d1 = ad_[colbase + 1],
                d2 = ad_[colbase + 2], d3 = ad_[colbase + 3];

    #pragma unroll
    for (int m = 0; m < 4; ++m) {
        float c0 = pair_sum(acc[m][0]);
        float c1 = pair_sum(acc[m][1]);
        float c2 = pair_sum(acc[m][2]);
        float c3 = pair_sum(acc[m][3]);
        float vs = c0 * a0 + c1 * a1 + c2 * a2 + c3 * a3;
        float vd = c0 * d0 + c1 * d1 + c2 * d2 + c3 * d3;
        #pragma unroll
        for (int off = 1; off < CGH; off <<= 1) {
            vs += __shfl_xor_sync(0xffffffffu, vs, off);
            vd += __shfl_xor_sync(0xffffffffu, vd, off);
        }
        int node = base + ng * 4 + m;
        if (node < N_NODES) {
            *(float4*)(h + (size_t)node * F_OUT + colbase) =
                make_float4(c0, c1, c2, c3);
            if ((cg & (CGH - 1)) == 0) {
                int head = cg / CGH;
                s_src[(size_t)node * HEADS + head] = vs;
                s_dst[(size_t)node * HEADS + head] = vd;
            }
        }
    }
}

// ---------------- gather aggregation: one (F_OUT/4)-lane group per dst ----------------
// Self-loop seeded analytically; edges walked from the dst-sorted CSR; row written
// once, coalesced, already normalized + bias (+relu). No atomics anywhere.
template<int F_OUT, bool RELU>
__global__ __launch_bounds__(256)
void aggregate_kernel(const float* __restrict__ h,
                      const float* __restrict__ s_src,
                      const float* __restrict__ s_dst,
                      const float* __restrict__ b,
                      float* __restrict__ out) {
    constexpr int LPD = F_OUT / 4;        // lanes per dst (32 / 16)
    constexpr int D   = F_OUT / HEADS;
    int gt  = blockIdx.x * 256 + threadIdx.x;
    int dst = gt / LPD;
    if (dst >= N_NODES) return;
    int sub  = gt % LPD;
    int head = (sub * 4) / D;

    float sd = s_dst[(size_t)dst * HEADS + head];

    // self-loop
    float ex = __expf(lrelu(s_src[(size_t)dst * HEADS + head] + sd));
    float4 hv = *(const float4*)(h + (size_t)dst * F_OUT + sub * 4);
    float ax = ex * hv.x, ay = ex * hv.y, az = ex * hv.z, aw = ex * hv.w;
    float den = ex;

    int i = g_off[dst], end = g_off[dst + 1];
    for (; i + 2 <= end; i += 2) {
        int s0 = g_src_sorted[i];
        int s1 = g_src_sorted[i + 1];
        float z0 = s_src[(size_t)s0 * HEADS + head];
        float z1 = s_src[(size_t)s1 * HEADS + head];
        float4 v0 = *(const float4*)(h + (size_t)s0 * F_OUT + sub * 4);
        float4 v1 = *(const float4*)(h + (size_t)s1 * F_OUT + sub * 4);
        float e0 = __expf(lrelu(z0 + sd));
        float e1 = __expf(lrelu(z1 + sd));
        ax = fmaf(e0, v0.x, ax); ay = fmaf(e0, v0.y, ay);
        az = fmaf(e0, v0.z, az); aw = fmaf(e0, v0.w, aw);
        ax = fmaf(e1, v1.x, ax); ay = fmaf(e1, v1.y, ay);
        az = fmaf(e1, v1.z, az); aw = fmaf(e1, v1.w, aw);
        den += e0 + e1;
    }
    if (i < end) {
        int s0 = g_src_sorted[i];
        float e0 = __expf(lrelu(s_src[(size_t)s0 * HEADS + head] + sd));
        float4 v0 = *(const float4*)(h + (size_t)s0 * F_OUT + sub * 4);
        ax = fmaf(e0, v0.x, ax); ay = fmaf(e0, v0.y, ay);
        az = fmaf(e0, v0.z, az); aw = fmaf(e0, v0.w, aw);
        den += e0;
    }

    float inv = 1.f / (den + 1e-16f);
    float4 bb = ((const float4*)b)[sub];
    float4 o;
    o.x = fmaf(ax, inv, bb.x);
    o.y = fmaf(ay, inv, bb.y);
    o.z = fmaf(az, inv, bb.z);
    o.w = fmaf(aw, inv, bb.w);
    if (RELU) {
        o.x = fmaxf(o.x, 0.f); o.y = fmaxf(o.y, 0.f);
        o.z = fmaxf(o.z, 0.f); o.w = fmaxf(o.w, 0.f);
    }
    *(float4*)(out + (size_t)dst * F_OUT + sub * 4) = o;
}

// ---------------- host launcher ----------------
extern "C" void kernel_launch(void* const* d_in, const int* in_sizes, int n_in,
                              void* d_out, int out_size) {
    const float* x     = (const float*)d_in[0];
    const void*  edges = d_in[1];
    const float* W1    = (const float*)d_in[2];
    const float* a1s   = (const float*)d_in[3];
    const float* a1d   = (const float*)d_in[4];
    const float* b1    = (const float*)d_in[5];
    const float* W2    = (const float*)d_in[6];
    const float* a2s   = (const float*)d_in[7];
    const float* a2d   = (const float*)d_in[8];
    const float* b2    = (const float*)d_in[9];
    float* outp = (float*)d_out;

    const int E = in_sizes[1] / 2;

    float *h1, *o1, *ss1, *sd1, *h2, *ss2, *sd2, *wt1, *wt2;
    int* degp;
    cudaGetSymbolAddress((void**)&h1,  g_h1);
    cudaGetSymbolAddress((void**)&o1,  g_out1);
    cudaGetSymbolAddress((void**)&ss1, g_s_src1);
    cudaGetSymbolAddress((void**)&sd1, g_s_dst1);
    cudaGetSymbolAddress((void**)&h2,  g_h2);
    cudaGetSymbolAddress((void**)&ss2, g_s_src2);
    cudaGetSymbolAddress((void**)&sd2, g_s_dst2);
    cudaGetSymbolAddress((void**)&wt1, g_WT1);
    cudaGetSymbolAddress((void**)&wt2, g_WT2);
    cudaGetSymbolAddress((void**)&degp, g_deg);

    constexpr int NT1 = 64, NT2 = 128;
    constexpr int XROW = F_IN + 4;
    const int smem1 = (F_IN * F1 + NT1 * XROW + 2 * F1) * (int)sizeof(float); // ~100 KB
    const int smem2 = (F_IN * F2 + NT2 * XROW + 2 * F2) * (int)sizeof(float); // ~101 KB
    cudaFuncSetAttribute((const void*)gemm_scores_kernel<F1, NT1>,
                         cudaFuncAttributeMaxDynamicSharedMemorySize, smem1);
    cudaFuncSetAttribute((const void*)gemm_scores_kernel<F2, NT2>,
                         cudaFuncAttributeMaxDynamicSharedMemorySize, smem2);

    const int eblocks = (E + 255) / 256;
    const int nscan   = (N_NODES + 511) / 512;   // 196 blocks

    // 0) dtype detect + weight transpose + CSR build
    detect_kernel<<<1, 256>>>((const long long*)edges);
    transpose_kernel<<<(F_IN * F1 + F_IN * F2 + 255) / 256, 256>>>(W1, W2);
    cudaMemsetAsync(degp, 0, N_NODES * sizeof(int));
    hist_kernel<<<eblocks, 256>>>(edges, E);
    scan1_kernel<<<nscan, 512>>>();
    scan2_kernel<<<1, 256>>>(nscan);
    scan3_kernel<<<nscan, 512>>>(E);
    scatter_kernel<<<eblocks, 256>>>(edges, E);

    // 1) layer 1: GEMM + scores (FFMA2)
    gemm_scores_kernel<F1, NT1><<<(N_NODES + NT1 - 1) / NT1, 512, smem1>>>(
        x, wt1, a1s, a1d, h1, ss1, sd1);

    // 2) layer 1: gather-aggregate (+normalize +bias +relu fused)
    aggregate_kernel<F1, true><<<(N_NODES * (F1 / 4) + 255) / 256, 256>>>(
        h1, ss1, sd1, b1, o1);

    // 3) layer 2: GEMM + scores (FFMA2)
    gemm_scores_kernel<F2, NT2><<<(N_NODES + NT2 - 1) / NT2, 512, smem2>>>(
        o1, wt2, a2s, a2d, h2, ss2, sd2);

    // 4) layer 2: gather-aggregate (+normalize +bias) -> final output
    aggregate_kernel<F2, false><<<(N_NODES * (F2 / 4) + 255) / 256, 256>>>(
        h2, ss2, sd2, b2, outp);
}